// round 15
// baseline (speedup 1.0000x reference)
#include <cuda_runtime.h>
#include <cuda_fp16.h>
#include <math.h>
#include <stdint.h>

#define N_NODES 50000
#define NTOT    (2 * N_NODES)
#define NEDGE   800000
#define ETOT    (2 * NEDGE)
#define M_TILES ((N_NODES + 127) / 128)   // 391 per graph
#define SCAN_BLOCKS_G ((N_NODES + 1023) / 1024)   // 49 per graph

// ================= device scratch =================
__device__ int   g_count[NTOT];
__device__ int   g_row_start[2 * (N_NODES + 1)];
__device__ int   g_cursor[NTOT];
__device__ int   g_srcsort[ETOT];
__device__ int   g_btot[2 * SCAN_BLOCKS_G];
__device__ __half g_xh16[(size_t)NTOT * 128];
__device__ __half g_af16[(size_t)NTOT * 128];
__device__ __half g_h16[(size_t)NTOT * 256];
__device__ __half g_v[(size_t)NTOT * 256];
__device__ __half g_p[(size_t)NTOT * 128];
__device__ __half g_q16[(size_t)NTOT * 128];
__device__ __half g_wf16[8 * 32768];

// ================= helpers =================
__device__ __forceinline__ uint32_t smem_u32(const void* p) {
    uint32_t a;
    asm("{ .reg .u64 t; cvta.to.shared.u64 t, %1; cvt.u32.u64 %0, t; }" : "=r"(a) : "l"(p));
    return a;
}
__device__ __forceinline__ void cp_async16(uint32_t dst, const void* src, bool valid) {
    if (valid) {
        asm volatile("cp.async.cg.shared.global [%0], [%1], 16;" :: "r"(dst), "l"(src));
    } else {
        asm volatile("cp.async.cg.shared.global [%0], [%1], 16, %2;"
                     :: "r"(dst), "l"(src), "r"(0u));
    }
}
#define CP_COMMIT()  asm volatile("cp.async.commit_group;" ::: "memory")
#define CP_WAIT1()   asm volatile("cp.async.wait_group 1;" ::: "memory")

__device__ __forceinline__ void ldsm4(uint32_t* r, uint32_t addr) {
    asm volatile("ldmatrix.sync.aligned.m8n8.x4.shared.b16 {%0,%1,%2,%3}, [%4];"
                 : "=r"(r[0]), "=r"(r[1]), "=r"(r[2]), "=r"(r[3]) : "r"(addr));
}
__device__ __forceinline__ void mma16816f16(float* d, const uint32_t* a, const uint32_t* b) {
    asm volatile(
        "mma.sync.aligned.m16n8k16.row.col.f32.f16.f16.f32 "
        "{%0,%1,%2,%3}, {%4,%5,%6,%7}, {%8,%9}, {%0,%1,%2,%3};"
        : "+f"(d[0]), "+f"(d[1]), "+f"(d[2]), "+f"(d[3])
        : "r"(a[0]), "r"(a[1]), "r"(a[2]), "r"(a[3]), "r"(b[0]), "r"(b[1]));
}

__device__ __forceinline__ float fast_tanh(float x) {
    float e = __expf(2.0f * x);
    return 1.0f - __fdividef(2.0f, e + 1.0f);
}

// ================= per-graph fp32 -> fp16 conversion (x + 4 weights) =============
struct Split5 {
    const float* src[5];
    __half* f16[5];
    int n4cum[6];
};

__global__ void split5_kernel(Split5 J) {
    int f = blockIdx.x * blockDim.x + threadIdx.x;
    if (f >= J.n4cum[5]) return;
    int j = 0;
#pragma unroll
    for (int t = 0; t < 5; t++)
        if (f >= J.n4cum[t + 1]) j = t + 1;
    int local = f - J.n4cum[j];
    float4 v = *(const float4*)(J.src[j] + 4 * (size_t)local);
    __half2 a = __floats2half2_rn(v.x, v.y);
    __half2 b = __floats2half2_rn(v.z, v.w);
    uint2 pk;
    pk.x = *(uint32_t*)&a;
    pk.y = *(uint32_t*)&b;
    *(uint2*)(J.f16[j] + 4 * (size_t)local) = pk;
}

// ================= per-graph CSR build =================
__global__ void hist_g_kernel(const int* __restrict__ ei, int* __restrict__ count) {
    int t = blockIdx.x * blockDim.x + threadIdx.x;
    int e = t * 2;
    if (e >= NEDGE) return;
    int2 d = *(const int2*)(ei + NEDGE + e);
    atomicAdd(&count[d.x], 1);
    atomicAdd(&count[d.y], 1);
}

// per-block exclusive scan over graph-local counts; zeroes counts; writes block totals
__global__ void scan_part_kernel(int* __restrict__ counts, int* __restrict__ row_start,
                                 int* __restrict__ btot) {
    __shared__ int wsum[32];
    int tid = threadIdx.x, lane = tid & 31, w = tid >> 5;
    int i = blockIdx.x * 1024 + tid;
    int v = 0;
    if (i < N_NODES) { v = counts[i]; counts[i] = 0; }
    int x = v;
#pragma unroll
    for (int off = 1; off < 32; off <<= 1) {
        int t = __shfl_up_sync(0xFFFFFFFFu, x, off);
        if (lane >= off) x += t;
    }
    if (lane == 31) wsum[w] = x;
    __syncthreads();
    if (w == 0) {
        int s = wsum[lane];
#pragma unroll
        for (int off = 1; off < 32; off <<= 1) {
            int t = __shfl_up_sync(0xFFFFFFFFu, s, off);
            if (lane >= off) s += t;
        }
        wsum[lane] = s;
    }
    __syncthreads();
    int excl = x - v + (w ? wsum[w - 1] : 0);
    if (i < N_NODES) row_start[i] = excl;
    if (tid == 0) btot[blockIdx.x] = wsum[31];
}

// each block redundantly scans the 49 block totals (no separate tops kernel),
// adds its offset + edge base; fills row_start[N_NODES] and cursor.
__global__ void scan_add_kernel(const int* __restrict__ btot, int* __restrict__ row_start,
                                int* __restrict__ cursor, int edge_base) {
    __shared__ int sh[64];
    int t = threadIdx.x;
    if (t < 64) sh[t] = (t < SCAN_BLOCKS_G) ? btot[t] : 0;
    __syncthreads();
    for (int off = 1; off < 64; off <<= 1) {
        int v = (t < 64 && t >= off) ? sh[t - off] : 0;
        __syncthreads();
        if (t < 64) sh[t] += v;
        __syncthreads();
    }
    int boff = (blockIdx.x > 0) ? sh[blockIdx.x - 1] : 0;
    int i = blockIdx.x * 1024 + t;
    if (i < N_NODES) {
        int rs = row_start[i] + boff + edge_base;
        row_start[i] = rs;
        cursor[i] = rs;
    }
    if (i == N_NODES - 1) row_start[N_NODES] = edge_base + NEDGE;
}

// 2 edges/thread, vectorized reads
__global__ void scatter_g_kernel(const int* __restrict__ ei, int node_base,
                                 int* __restrict__ cursor, int* __restrict__ srcsort) {
    int t = blockIdx.x * blockDim.x + threadIdx.x;
    int e = t * 2;
    if (e >= NEDGE) return;
    int2 s = *(const int2*)(ei + e);
    int2 d = *(const int2*)(ei + NEDGE + e);
    int p0 = atomicAdd(&cursor[d.x], 1);
    srcsort[p0] = s.x + node_base;
    int p1 = atomicAdd(&cursor[d.y], 1);
    srcsort[p1] = s.y + node_base;
}

// ================= layer-1 mean aggregation (16B loads, 8 nodes/block) ============
__global__ void aggregate1_kernel(const __half* __restrict__ xh,
                                  const int* __restrict__ rs,
                                  const int* __restrict__ srcsort,
                                  __half* __restrict__ oa, int node_base) {
    int local = threadIdx.x >> 4;
    int t8 = (threadIdx.x & 15) * 8;
    int ln = blockIdx.x * 8 + local;
    int node = node_base + ln;
    int s0 = rs[ln];
    int s1 = rs[ln + 1];
    float a[8];
#pragma unroll
    for (int i = 0; i < 8; i++) a[i] = 0.f;
    int e = s0;
    for (; e + 2 <= s1; e += 2) {
        uint4 vA = *(const uint4*)(xh + (size_t)srcsort[e] * 128 + t8);
        uint4 vB = *(const uint4*)(xh + (size_t)srcsort[e + 1] * 128 + t8);
        const uint32_t* wA = &vA.x;
        const uint32_t* wB = &vB.x;
#pragma unroll
        for (int i = 0; i < 4; i++) {
            float2 fA = __half22float2(*(__half2*)&wA[i]);
            float2 fB = __half22float2(*(__half2*)&wB[i]);
            a[2 * i] += fA.x + fB.x;
            a[2 * i + 1] += fA.y + fB.y;
        }
    }
    if (e < s1) {
        uint4 v = *(const uint4*)(xh + (size_t)srcsort[e] * 128 + t8);
        const uint32_t* w = &v.x;
#pragma unroll
        for (int i = 0; i < 4; i++) {
            float2 f = __half22float2(*(__half2*)&w[i]);
            a[2 * i] += f.x;
            a[2 * i + 1] += f.y;
        }
    }
    float inv = 1.0f / (float)max(s1 - s0, 1);
    uint4 pk;
    uint32_t* pw = &pk.x;
#pragma unroll
    for (int i = 0; i < 4; i++) {
        __half2 h = __floats2half2_rn(a[2 * i] * inv, a[2 * i + 1] * inv);
        pw[i] = *(uint32_t*)&h;
    }
    *(uint4*)(oa + (size_t)node * 128 + t8) = pk;
}

// ================= layer-2 fused aggregation + epilogue =================
__global__ void agg_fuse2_kernel(const __half* __restrict__ p,
                                 const __half* __restrict__ q,
                                 const int* __restrict__ rs,
                                 const int* __restrict__ srcsort,
                                 const float* __restrict__ bias,
                                 float* __restrict__ out, int node_base) {
    int local = threadIdx.x >> 4;
    int t8 = (threadIdx.x & 15) * 8;
    int ln = blockIdx.x * 8 + local;
    int node = node_base + ln;
    int s0 = rs[ln];
    int s1 = rs[ln + 1];
    float a[8];
#pragma unroll
    for (int i = 0; i < 8; i++) a[i] = 0.f;
    int e = s0;
    for (; e + 2 <= s1; e += 2) {
        uint4 vA = *(const uint4*)(p + (size_t)srcsort[e] * 128 + t8);
        uint4 vB = *(const uint4*)(p + (size_t)srcsort[e + 1] * 128 + t8);
        const uint32_t* wA = &vA.x;
        const uint32_t* wB = &vB.x;
#pragma unroll
        for (int i = 0; i < 4; i++) {
            float2 fA = __half22float2(*(__half2*)&wA[i]);
            float2 fB = __half22float2(*(__half2*)&wB[i]);
            a[2 * i] += fA.x + fB.x;
            a[2 * i + 1] += fA.y + fB.y;
        }
    }
    if (e < s1) {
        uint4 v = *(const uint4*)(p + (size_t)srcsort[e] * 128 + t8);
        const uint32_t* w = &v.x;
#pragma unroll
        for (int i = 0; i < 4; i++) {
            float2 f = __half22float2(*(__half2*)&w[i]);
            a[2 * i] += f.x;
            a[2 * i + 1] += f.y;
        }
    }
    float inv = 1.0f / (float)max(s1 - s0, 1);
    uint4 qv = *(const uint4*)(q + (size_t)node * 128 + t8);
    const uint32_t* qw = &qv.x;
    float4 b0 = *(const float4*)(bias + t8);
    float4 b1 = *(const float4*)(bias + t8 + 4);
    float qq[8];
#pragma unroll
    for (int i = 0; i < 4; i++) {
        float2 f = __half22float2(*(__half2*)&qw[i]);
        qq[2 * i] = f.x;
        qq[2 * i + 1] = f.y;
    }
    float4 o0, o1;
    o0.x = fast_tanh(a[0] * inv + qq[0] + b0.x);
    o0.y = fast_tanh(a[1] * inv + qq[1] + b0.y);
    o0.z = fast_tanh(a[2] * inv + qq[2] + b0.z);
    o0.w = fast_tanh(a[3] * inv + qq[3] + b0.w);
    o1.x = fast_tanh(a[4] * inv + qq[4] + b1.x);
    o1.y = fast_tanh(a[5] * inv + qq[5] + b1.y);
    o1.z = fast_tanh(a[6] * inv + qq[6] + b1.z);
    o1.w = fast_tanh(a[7] * inv + qq[7] + b1.w);
    *(float4*)(out + (size_t)node * 128 + t8) = o0;
    *(float4*)(out + (size_t)node * 128 + t8 + 4) = o1;
}

// ================= fp16 mma.sync GEMM =================
struct GemmW {
    const __half* b0[2][2];
    const __half* b1[2][2];
    const float* bias[2];
};

// MODE 1: layer2 p/q ; MODE 2: v = x@W1r^T ; MODE 3: h = tanh(acc+v+bias)
template <int KHALF, int ASTRIDE, int BSTRIDE, int BOFF, int MODE>
__global__ void __launch_bounds__(256, 2)
sage_mma_kernel(const __half* __restrict__ a0, const __half* __restrict__ a1,
                GemmW W,
                __half* __restrict__ oh, __half* __restrict__ op,
                __half* __restrict__ oq, const __half* __restrict__ vin, int gbase) {
    constexpr int NC = 2 * KHALF / 32;
    constexpr int MATB = 10240;
    constexpr int STAGE = 2 * MATB;
    constexpr int MT = 4;

    extern __shared__ char smem[];
    uint32_t sb = smem_u32(smem);

    int tid = threadIdx.x;
    int wid = tid >> 5;
    int lane = tid & 31;
    int wm = wid & 1;
    int wn = wid >> 1;
    int y = blockIdx.y;
    int g = gbase + blockIdx.z;
    int m0 = g * N_NODES + blockIdx.x * 128;
    int Mlim = (g + 1) * N_NODES;
    int n0 = y * 128;
    int bn0 = y * BOFF;

    const __half* B0 = W.b0[y][g];
    const __half* B1 = W.b1[y][g];

    auto issue = [&](int c) {
        int half = (c * 32 >= KHALF) ? 1 : 0;
        int kh0 = c * 32 - half * KHALF;
        const __half* A = half ? a1 : a0;
        const __half* B = half ? B1 : B0;
        uint32_t st = sb + (c & 1) * STAGE;
#pragma unroll
        for (int i = 0; i < 4; i++) {
            int idx = i * 256 + tid;
            int r = idx >> 2;
            int ch = idx & 3;
            if (r < 128) {
                int m = m0 + r;
                bool valid = (m < Mlim);
                const __half* pp = A + (size_t)(valid ? m : 0) * ASTRIDE + kh0 + ch * 8;
                cp_async16(st + r * 80 + ch * 16, pp, valid);
            } else {
                int rl = r - 128;
                cp_async16(st + MATB + rl * 80 + ch * 16,
                           B + (size_t)(bn0 + rl) * BSTRIDE + kh0 + ch * 8, true);
            }
        }
    };

    float acc[MT][4][4];
#pragma unroll
    for (int i = 0; i < MT; i++)
#pragma unroll
        for (int j = 0; j < 4; j++)
#pragma unroll
            for (int k = 0; k < 4; k++) acc[i][j][k] = 0.f;

    issue(0); CP_COMMIT();
    issue(1); CP_COMMIT();

    uint32_t a_row = (uint32_t)(wm * 64 + (lane & 15)) * 80 + (lane >> 4) * 16;
    uint32_t b_row = (uint32_t)(wn * 32 + (lane & 7) + ((lane >> 4) << 3)) * 80 +
                     ((lane >> 3) & 1) * 16;

    for (int c = 0; c < NC; c++) {
        CP_WAIT1();
        __syncthreads();
        uint32_t st = sb + (c & 1) * STAGE;
#pragma unroll
        for (int ks = 0; ks < 2; ks++) {
            uint32_t ko = ks * 32;
            uint32_t Af[MT][4], Bf[2][4];
#pragma unroll
            for (int mt = 0; mt < MT; mt++)
                ldsm4(Af[mt], st + a_row + (uint32_t)mt * (16 * 80) + ko);
#pragma unroll
            for (int nt2 = 0; nt2 < 2; nt2++)
                ldsm4(Bf[nt2], st + MATB + b_row + (uint32_t)nt2 * (16 * 80) + ko);
#pragma unroll
            for (int mt = 0; mt < MT; mt++) {
#pragma unroll
                for (int nt = 0; nt < 4; nt++) {
                    mma16816f16(acc[mt][nt], Af[mt], &Bf[nt >> 1][(nt & 1) * 2]);
                }
            }
        }
        __syncthreads();
        if (c + 2 < NC) issue(c + 2);
        CP_COMMIT();
    }

    int gq = lane >> 2, t4 = lane & 3;
    const float* bias = (MODE == 3) ? W.bias[g] : nullptr;
#pragma unroll
    for (int mt = 0; mt < MT; mt++) {
#pragma unroll
        for (int nt = 0; nt < 4; nt++) {
            int col = wn * 32 + nt * 8 + 2 * t4;
            float b0 = (MODE == 3) ? bias[n0 + col] : 0.f;
            float b1 = (MODE == 3) ? bias[n0 + col + 1] : 0.f;
#pragma unroll
            for (int hrow = 0; hrow < 2; hrow++) {
                int row = m0 + wm * 64 + mt * 16 + gq + hrow * 8;
                if (row < Mlim) {
                    float v0 = acc[mt][nt][2 * hrow + 0];
                    float v1 = acc[mt][nt][2 * hrow + 1];
                    if (MODE == 1) {
                        size_t ob = (size_t)row * 128 + col;
                        __half2 h = __floats2half2_rn(v0, v1);
                        if (y == 0) *(__half2*)(op + ob) = h;
                        else        *(__half2*)(oq + ob) = h;
                    } else if (MODE == 2) {
                        size_t ob = (size_t)row * 256 + n0 + col;
                        *(__half2*)(op + ob) = __floats2half2_rn(v0, v1);
                    } else {
                        size_t ob = (size_t)row * 256 + n0 + col;
                        float2 vv = __half22float2(*(const __half2*)(vin + ob));
                        v0 = fast_tanh(v0 + vv.x + b0);
                        v1 = fast_tanh(v1 + vv.y + b1);
                        *(__half2*)(oh + ob) = __floats2half2_rn(v0, v1);
                    }
                }
            }
        }
    }
}

// ================= host =================
extern "C" void kernel_launch(void* const* d_in, const int* in_sizes, int n_in,
                              void* d_out, int out_size) {
    (void)in_sizes; (void)n_in; (void)out_size;

    const float* x0  = (const float*)d_in[0];
    const float* x1  = (const float*)d_in[1];
    const int*   ei0 = (const int*)d_in[2];
    const int*   ei1 = (const int*)d_in[3];
    const float* W1l_0 = (const float*)d_in[4];
    const float* b1_0  = (const float*)d_in[5];
    const float* W1r_0 = (const float*)d_in[6];
    const float* W2l_0 = (const float*)d_in[7];
    const float* b2_0  = (const float*)d_in[8];
    const float* W2r_0 = (const float*)d_in[9];
    const float* W1l_1 = (const float*)d_in[10];
    const float* b1_1  = (const float*)d_in[11];
    const float* W1r_1 = (const float*)d_in[12];
    const float* W2l_1 = (const float*)d_in[13];
    const float* b2_1  = (const float*)d_in[14];
    const float* W2r_1 = (const float*)d_in[15];
    float* out = (float*)d_out;

    constexpr int SMEM = 2 * 2 * 10240;  // 40960

    int *count, *row_start, *cursor, *srcsort, *btot;
    __half *xh16, *af16, *h16, *v, *p, *q16, *wf16;
    cudaGetSymbolAddress((void**)&count, g_count);
    cudaGetSymbolAddress((void**)&row_start, g_row_start);
    cudaGetSymbolAddress((void**)&cursor, g_cursor);
    cudaGetSymbolAddress((void**)&srcsort, g_srcsort);
    cudaGetSymbolAddress((void**)&btot, g_btot);
    cudaGetSymbolAddress((void**)&xh16, g_xh16);
    cudaGetSymbolAddress((void**)&af16, g_af16);
    cudaGetSymbolAddress((void**)&h16, g_h16);
    cudaGetSymbolAddress((void**)&v, g_v);
    cudaGetSymbolAddress((void**)&p, g_p);
    cudaGetSymbolAddress((void**)&q16, g_q16);
    cudaGetSymbolAddress((void**)&wf16, g_wf16);

    // per-graph split jobs: x_g + W1l_g, W1r_g, W2l_g, W2r_g
    Split5 S[2];
    const float* xs[2] = {x0, x1};
    const float* ws[2][4] = {{W1l_0, W1r_0, W2l_0, W2r_0}, {W1l_1, W1r_1, W2l_1, W2r_1}};
    int cumG[2];
    for (int g = 0; g < 2; g++) {
        int cum = 0;
        S[g].src[0] = xs[g];
        S[g].f16[0] = xh16 + (size_t)g * N_NODES * 128;
        S[g].n4cum[0] = 0;
        cum = N_NODES * 128 / 4;
        for (int j = 0; j < 4; j++) {
            S[g].src[j + 1] = ws[g][j];
            S[g].f16[j + 1] = wf16 + (4 * g + j) * 32768;
            S[g].n4cum[j + 1] = cum;
            cum += 32768 / 4;
        }
        S[g].n4cum[5] = cum;
        cumG[g] = cum;
    }

    GemmW Wv, Wu, W2;
    for (int g = 0; g < 2; g++) {
        for (int y = 0; y < 2; y++) {
            Wv.b0[y][g] = wf16 + (4 * g + 1) * 32768;
            Wv.b1[y][g] = wf16 + (4 * g + 1) * 32768 + 64;
            Wu.b0[y][g] = wf16 + (4 * g + 0) * 32768;
            Wu.b1[y][g] = wf16 + (4 * g + 0) * 32768 + 64;
        }
        W2.b0[0][g] = wf16 + (4 * g + 2) * 32768;
        W2.b1[0][g] = wf16 + (4 * g + 2) * 32768 + 128;
        W2.b0[1][g] = wf16 + (4 * g + 3) * 32768;
        W2.b1[1][g] = wf16 + (4 * g + 3) * 32768 + 128;
    }
    Wu.bias[0] = b1_0; Wu.bias[1] = b1_1;
    Wv.bias[0] = nullptr; Wv.bias[1] = nullptr;
    W2.bias[0] = nullptr; W2.bias[1] = nullptr;

    int* rs0 = row_start;
    int* rs1 = row_start + (N_NODES + 1);
    int* cur0 = cursor;
    int* cur1 = cursor + N_NODES;
    int* cnt0 = count;
    int* cnt1 = count + N_NODES;

    cudaStream_t s2, s3;
    cudaStreamCreateWithFlags(&s2, cudaStreamNonBlocking);
    cudaStreamCreateWithFlags(&s3, cudaStreamNonBlocking);
    cudaEvent_t evFork, evS0, evS1, evV0, evV1, evD1;
    cudaEventCreateWithFlags(&evFork, cudaEventDisableTiming);
    cudaEventCreateWithFlags(&evS0, cudaEventDisableTiming);
    cudaEventCreateWithFlags(&evS1, cudaEventDisableTiming);
    cudaEventCreateWithFlags(&evV0, cudaEventDisableTiming);
    cudaEventCreateWithFlags(&evV1, cudaEventDisableTiming);
    cudaEventCreateWithFlags(&evD1, cudaEventDisableTiming);

    cudaEventRecord(evFork, 0);
    cudaStreamWaitEvent(s2, evFork, 0);
    cudaStreamWaitEvent(s3, evFork, 0);

    // s2: split(g0) -> v(g0) -> split(g1) -> v(g1)
    split5_kernel<<<(cumG[0] + 255) / 256, 256, 0, s2>>>(S[0]);
    cudaEventRecord(evS0, s2);
    {
        dim3 grid(M_TILES, 2, 1);
        sage_mma_kernel<64, 128, 128, 128, 2><<<grid, 256, SMEM, s2>>>(
            xh16, xh16 + 64, Wv, nullptr, v, nullptr, nullptr, 0);
    }
    cudaEventRecord(evV0, s2);
    split5_kernel<<<(cumG[1] + 255) / 256, 256, 0, s2>>>(S[1]);
    cudaEventRecord(evS1, s2);
    {
        dim3 grid(M_TILES, 2, 1);
        sage_mma_kernel<64, 128, 128, 128, 2><<<grid, 256, SMEM, s2>>>(
            xh16, xh16 + 64, Wv, nullptr, v, nullptr, nullptr, 1);
    }
    cudaEventRecord(evV1, s2);

    // ===== graph-0 chain on main =====
    hist_g_kernel<<<(NEDGE / 2 + 255) / 256, 256>>>(ei0, cnt0);
    scan_part_kernel<<<SCAN_BLOCKS_G, 1024>>>(cnt0, rs0, btot);
    scan_add_kernel<<<SCAN_BLOCKS_G, 1024>>>(btot, rs0, cur0, 0);
    scatter_g_kernel<<<(NEDGE / 2 + 255) / 256, 256>>>(ei0, 0, cur0, srcsort);
    cudaStreamWaitEvent(0, evS0, 0);
    aggregate1_kernel<<<N_NODES / 8, 128>>>(xh16, rs0, srcsort, af16, 0);
    cudaStreamWaitEvent(0, evV0, 0);
    {
        dim3 grid(M_TILES, 2, 1);
        sage_mma_kernel<64, 128, 128, 128, 3><<<grid, 256, SMEM>>>(
            af16, af16 + 64, Wu, h16, nullptr, nullptr, v, 0);
        sage_mma_kernel<128, 256, 256, 0, 1><<<grid, 256, SMEM>>>(
            h16, h16 + 128, W2, nullptr, p, q16, nullptr, 0);
    }
    agg_fuse2_kernel<<<N_NODES / 8, 128>>>(p, q16, rs0, srcsort, b2_0, out, 0);

    // ===== graph-1 chain on s3 =====
    hist_g_kernel<<<(NEDGE / 2 + 255) / 256, 256, 0, s3>>>(ei1, cnt1);
    scan_part_kernel<<<SCAN_BLOCKS_G, 1024, 0, s3>>>(cnt1, rs1, btot + SCAN_BLOCKS_G);
    scan_add_kernel<<<SCAN_BLOCKS_G, 1024, 0, s3>>>(btot + SCAN_BLOCKS_G, rs1, cur1, NEDGE);
    scatter_g_kernel<<<(NEDGE / 2 + 255) / 256, 256, 0, s3>>>(ei1, N_NODES, cur1, srcsort);
    cudaStreamWaitEvent(s3, evS1, 0);
    aggregate1_kernel<<<N_NODES / 8, 128, 0, s3>>>(xh16, rs1, srcsort, af16, N_NODES);
    cudaStreamWaitEvent(s3, evV1, 0);
    {
        dim3 grid(M_TILES, 2, 1);
        sage_mma_kernel<64, 128, 128, 128, 3><<<grid, 256, SMEM, s3>>>(
            af16, af16 + 64, Wu, h16, nullptr, nullptr, v, 1);
        sage_mma_kernel<128, 256, 256, 0, 1><<<grid, 256, SMEM, s3>>>(
            h16, h16 + 128, W2, nullptr, p, q16, nullptr, 1);
    }
    agg_fuse2_kernel<<<N_NODES / 8, 128, 0, s3>>>(p, q16, rs1, srcsort, b2_1, out, N_NODES);
    cudaEventRecord(evD1, s3);

    cudaStreamWaitEvent(0, evD1, 0);

    cudaEventDestroy(evFork);
    cudaEventDestroy(evS0);
    cudaEventDestroy(evS1);
    cudaEventDestroy(evV0);
    cudaEventDestroy(evV1);
    cudaEventDestroy(evD1);
    cudaStreamDestroy(s2);
    cudaStreamDestroy(s3);
}

// round 16
// speedup vs baseline: 1.0074x; 1.0074x over previous
#include <cuda_runtime.h>
#include <cuda_fp16.h>
#include <math.h>
#include <stdint.h>

#define N_NODES 50000
#define NTOT    (2 * N_NODES)
#define NEDGE   800000
#define ETOT    (2 * NEDGE)
#define M_TILES ((N_NODES + 127) / 128)   // 391 per graph
#define SCAN_BLOCKS_G ((N_NODES + 1023) / 1024)   // 49 per graph

// ================= device scratch =================
__device__ int   g_count[NTOT];
__device__ int   g_row_start[2 * (N_NODES + 1)];
__device__ int   g_cursor[NTOT];
__device__ int   g_srcsort[ETOT];
__device__ int   g_btot[2 * SCAN_BLOCKS_G];
__device__ __half g_xh16[(size_t)NTOT * 128];
__device__ __half g_af16[(size_t)NTOT * 128];
__device__ __half g_h16[(size_t)NTOT * 256];
__device__ __half g_v[(size_t)NTOT * 256];
__device__ __half g_p[(size_t)NTOT * 128];
__device__ __half g_q16[(size_t)NTOT * 128];
__device__ __half g_wf16[8 * 32768];

// ================= helpers =================
__device__ __forceinline__ uint32_t smem_u32(const void* p) {
    uint32_t a;
    asm("{ .reg .u64 t; cvta.to.shared.u64 t, %1; cvt.u32.u64 %0, t; }" : "=r"(a) : "l"(p));
    return a;
}
__device__ __forceinline__ void cp_async16(uint32_t dst, const void* src, bool valid) {
    if (valid) {
        asm volatile("cp.async.cg.shared.global [%0], [%1], 16;" :: "r"(dst), "l"(src));
    } else {
        asm volatile("cp.async.cg.shared.global [%0], [%1], 16, %2;"
                     :: "r"(dst), "l"(src), "r"(0u));
    }
}
#define CP_COMMIT()  asm volatile("cp.async.commit_group;" ::: "memory")
#define CP_WAIT1()   asm volatile("cp.async.wait_group 1;" ::: "memory")

__device__ __forceinline__ void ldsm4(uint32_t* r, uint32_t addr) {
    asm volatile("ldmatrix.sync.aligned.m8n8.x4.shared.b16 {%0,%1,%2,%3}, [%4];"
                 : "=r"(r[0]), "=r"(r[1]), "=r"(r[2]), "=r"(r[3]) : "r"(addr));
}
__device__ __forceinline__ void mma16816f16(float* d, const uint32_t* a, const uint32_t* b) {
    asm volatile(
        "mma.sync.aligned.m16n8k16.row.col.f32.f16.f16.f32 "
        "{%0,%1,%2,%3}, {%4,%5,%6,%7}, {%8,%9}, {%0,%1,%2,%3};"
        : "+f"(d[0]), "+f"(d[1]), "+f"(d[2]), "+f"(d[3])
        : "r"(a[0]), "r"(a[1]), "r"(a[2]), "r"(a[3]), "r"(b[0]), "r"(b[1]));
}

__device__ __forceinline__ float fast_tanh(float x) {
    float e = __expf(2.0f * x);
    return 1.0f - __fdividef(2.0f, e + 1.0f);
}

// ================= per-graph fp32 -> fp16 conversion (x + 4 weights) =============
struct Split5 {
    const float* src[5];
    __half* f16[5];
    int n4cum[6];
};

__global__ void split5_kernel(Split5 J) {
    int f = blockIdx.x * blockDim.x + threadIdx.x;
    if (f >= J.n4cum[5]) return;
    int j = 0;
#pragma unroll
    for (int t = 0; t < 5; t++)
        if (f >= J.n4cum[t + 1]) j = t + 1;
    int local = f - J.n4cum[j];
    float4 v = *(const float4*)(J.src[j] + 4 * (size_t)local);
    __half2 a = __floats2half2_rn(v.x, v.y);
    __half2 b = __floats2half2_rn(v.z, v.w);
    uint2 pk;
    pk.x = *(uint32_t*)&a;
    pk.y = *(uint32_t*)&b;
    *(uint2*)(J.f16[j] + 4 * (size_t)local) = pk;
}

// ================= per-graph CSR build =================
__global__ void hist_g_kernel(const int* __restrict__ ei, int* __restrict__ count) {
    int t = blockIdx.x * blockDim.x + threadIdx.x;
    int e = t * 2;
    if (e >= NEDGE) return;
    int2 d = *(const int2*)(ei + NEDGE + e);
    atomicAdd(&count[d.x], 1);
    atomicAdd(&count[d.y], 1);
}

// per-block exclusive scan over graph-local counts; zeroes counts; writes block totals
__global__ void scan_part_kernel(int* __restrict__ counts, int* __restrict__ row_start,
                                 int* __restrict__ btot) {
    __shared__ int wsum[32];
    int tid = threadIdx.x, lane = tid & 31, w = tid >> 5;
    int i = blockIdx.x * 1024 + tid;
    int v = 0;
    if (i < N_NODES) { v = counts[i]; counts[i] = 0; }
    int x = v;
#pragma unroll
    for (int off = 1; off < 32; off <<= 1) {
        int t = __shfl_up_sync(0xFFFFFFFFu, x, off);
        if (lane >= off) x += t;
    }
    if (lane == 31) wsum[w] = x;
    __syncthreads();
    if (w == 0) {
        int s = wsum[lane];
#pragma unroll
        for (int off = 1; off < 32; off <<= 1) {
            int t = __shfl_up_sync(0xFFFFFFFFu, s, off);
            if (lane >= off) s += t;
        }
        wsum[lane] = s;
    }
    __syncthreads();
    int excl = x - v + (w ? wsum[w - 1] : 0);
    if (i < N_NODES) row_start[i] = excl;
    if (tid == 0) btot[blockIdx.x] = wsum[31];
}

// each block redundantly scans the 49 block totals (no separate tops kernel),
// adds its offset + edge base; fills row_start[N_NODES] and cursor.
__global__ void scan_add_kernel(const int* __restrict__ btot, int* __restrict__ row_start,
                                int* __restrict__ cursor, int edge_base) {
    __shared__ int sh[64];
    int t = threadIdx.x;
    if (t < 64) sh[t] = (t < SCAN_BLOCKS_G) ? btot[t] : 0;
    __syncthreads();
    for (int off = 1; off < 64; off <<= 1) {
        int v = (t < 64 && t >= off) ? sh[t - off] : 0;
        __syncthreads();
        if (t < 64) sh[t] += v;
        __syncthreads();
    }
    int boff = (blockIdx.x > 0) ? sh[blockIdx.x - 1] : 0;
    int i = blockIdx.x * 1024 + t;
    if (i < N_NODES) {
        int rs = row_start[i] + boff + edge_base;
        row_start[i] = rs;
        cursor[i] = rs;
    }
    if (i == N_NODES - 1) row_start[N_NODES] = edge_base + NEDGE;
}

// 2 edges/thread, vectorized reads
__global__ void scatter_g_kernel(const int* __restrict__ ei, int node_base,
                                 int* __restrict__ cursor, int* __restrict__ srcsort) {
    int t = blockIdx.x * blockDim.x + threadIdx.x;
    int e = t * 2;
    if (e >= NEDGE) return;
    int2 s = *(const int2*)(ei + e);
    int2 d = *(const int2*)(ei + NEDGE + e);
    int p0 = atomicAdd(&cursor[d.x], 1);
    srcsort[p0] = s.x + node_base;
    int p1 = atomicAdd(&cursor[d.y], 1);
    srcsort[p1] = s.y + node_base;
}

// ================= layer-1 mean aggregation (16B loads, 8 nodes/block) ============
__global__ void aggregate1_kernel(const __half* __restrict__ xh,
                                  const int* __restrict__ rs,
                                  const int* __restrict__ srcsort,
                                  __half* __restrict__ oa, int node_base) {
    int local = threadIdx.x >> 4;
    int t8 = (threadIdx.x & 15) * 8;
    int ln = blockIdx.x * 8 + local;
    int node = node_base + ln;
    int s0 = rs[ln];
    int s1 = rs[ln + 1];
    float a[8];
#pragma unroll
    for (int i = 0; i < 8; i++) a[i] = 0.f;
    int e = s0;
    for (; e + 2 <= s1; e += 2) {
        uint4 vA = *(const uint4*)(xh + (size_t)srcsort[e] * 128 + t8);
        uint4 vB = *(const uint4*)(xh + (size_t)srcsort[e + 1] * 128 + t8);
        const uint32_t* wA = &vA.x;
        const uint32_t* wB = &vB.x;
#pragma unroll
        for (int i = 0; i < 4; i++) {
            float2 fA = __half22float2(*(__half2*)&wA[i]);
            float2 fB = __half22float2(*(__half2*)&wB[i]);
            a[2 * i] += fA.x + fB.x;
            a[2 * i + 1] += fA.y + fB.y;
        }
    }
    if (e < s1) {
        uint4 v = *(const uint4*)(xh + (size_t)srcsort[e] * 128 + t8);
        const uint32_t* w = &v.x;
#pragma unroll
        for (int i = 0; i < 4; i++) {
            float2 f = __half22float2(*(__half2*)&w[i]);
            a[2 * i] += f.x;
            a[2 * i + 1] += f.y;
        }
    }
    float inv = 1.0f / (float)max(s1 - s0, 1);
    uint4 pk;
    uint32_t* pw = &pk.x;
#pragma unroll
    for (int i = 0; i < 4; i++) {
        __half2 h = __floats2half2_rn(a[2 * i] * inv, a[2 * i + 1] * inv);
        pw[i] = *(uint32_t*)&h;
    }
    *(uint4*)(oa + (size_t)node * 128 + t8) = pk;
}

// ================= layer-2 fused aggregation + epilogue =================
__global__ void agg_fuse2_kernel(const __half* __restrict__ p,
                                 const __half* __restrict__ q,
                                 const int* __restrict__ rs,
                                 const int* __restrict__ srcsort,
                                 const float* __restrict__ bias,
                                 float* __restrict__ out, int node_base) {
    int local = threadIdx.x >> 4;
    int t8 = (threadIdx.x & 15) * 8;
    int ln = blockIdx.x * 8 + local;
    int node = node_base + ln;
    int s0 = rs[ln];
    int s1 = rs[ln + 1];
    float a[8];
#pragma unroll
    for (int i = 0; i < 8; i++) a[i] = 0.f;
    int e = s0;
    for (; e + 2 <= s1; e += 2) {
        uint4 vA = *(const uint4*)(p + (size_t)srcsort[e] * 128 + t8);
        uint4 vB = *(const uint4*)(p + (size_t)srcsort[e + 1] * 128 + t8);
        const uint32_t* wA = &vA.x;
        const uint32_t* wB = &vB.x;
#pragma unroll
        for (int i = 0; i < 4; i++) {
            float2 fA = __half22float2(*(__half2*)&wA[i]);
            float2 fB = __half22float2(*(__half2*)&wB[i]);
            a[2 * i] += fA.x + fB.x;
            a[2 * i + 1] += fA.y + fB.y;
        }
    }
    if (e < s1) {
        uint4 v = *(const uint4*)(p + (size_t)srcsort[e] * 128 + t8);
        const uint32_t* w = &v.x;
#pragma unroll
        for (int i = 0; i < 4; i++) {
            float2 f = __half22float2(*(__half2*)&w[i]);
            a[2 * i] += f.x;
            a[2 * i + 1] += f.y;
        }
    }
    float inv = 1.0f / (float)max(s1 - s0, 1);
    uint4 qv = *(const uint4*)(q + (size_t)node * 128 + t8);
    const uint32_t* qw = &qv.x;
    float4 b0 = *(const float4*)(bias + t8);
    float4 b1 = *(const float4*)(bias + t8 + 4);
    float qq[8];
#pragma unroll
    for (int i = 0; i < 4; i++) {
        float2 f = __half22float2(*(__half2*)&qw[i]);
        qq[2 * i] = f.x;
        qq[2 * i + 1] = f.y;
    }
    float4 o0, o1;
    o0.x = fast_tanh(a[0] * inv + qq[0] + b0.x);
    o0.y = fast_tanh(a[1] * inv + qq[1] + b0.y);
    o0.z = fast_tanh(a[2] * inv + qq[2] + b0.z);
    o0.w = fast_tanh(a[3] * inv + qq[3] + b0.w);
    o1.x = fast_tanh(a[4] * inv + qq[4] + b1.x);
    o1.y = fast_tanh(a[5] * inv + qq[5] + b1.y);
    o1.z = fast_tanh(a[6] * inv + qq[6] + b1.z);
    o1.w = fast_tanh(a[7] * inv + qq[7] + b1.w);
    *(float4*)(out + (size_t)node * 128 + t8) = o0;
    *(float4*)(out + (size_t)node * 128 + t8 + 4) = o1;
}

// ================= fp16 mma.sync GEMM =================
struct GemmW {
    const __half* b0[2][2];
    const __half* b1[2][2];
    const float* bias[2];
};

// MODE 1: layer2 p/q ; MODE 2: v = x@W1r^T ; MODE 3: h = tanh(acc+v+bias)
template <int KHALF, int ASTRIDE, int BSTRIDE, int BOFF, int MODE>
__global__ void __launch_bounds__(256, 2)
sage_mma_kernel(const __half* __restrict__ a0, const __half* __restrict__ a1,
                GemmW W,
                __half* __restrict__ oh, __half* __restrict__ op,
                __half* __restrict__ oq, const __half* __restrict__ vin, int gbase) {
    constexpr int NC = 2 * KHALF / 32;
    constexpr int MATB = 10240;
    constexpr int STAGE = 2 * MATB;
    constexpr int MT = 4;

    extern __shared__ char smem[];
    uint32_t sb = smem_u32(smem);

    int tid = threadIdx.x;
    int wid = tid >> 5;
    int lane = tid & 31;
    int wm = wid & 1;
    int wn = wid >> 1;
    int y = blockIdx.y;
    int g = gbase + blockIdx.z;
    int m0 = g * N_NODES + blockIdx.x * 128;
    int Mlim = (g + 1) * N_NODES;
    int n0 = y * 128;
    int bn0 = y * BOFF;

    const __half* B0 = W.b0[y][g];
    const __half* B1 = W.b1[y][g];

    auto issue = [&](int c) {
        int half = (c * 32 >= KHALF) ? 1 : 0;
        int kh0 = c * 32 - half * KHALF;
        const __half* A = half ? a1 : a0;
        const __half* B = half ? B1 : B0;
        uint32_t st = sb + (c & 1) * STAGE;
#pragma unroll
        for (int i = 0; i < 4; i++) {
            int idx = i * 256 + tid;
            int r = idx >> 2;
            int ch = idx & 3;
            if (r < 128) {
                int m = m0 + r;
                bool valid = (m < Mlim);
                const __half* pp = A + (size_t)(valid ? m : 0) * ASTRIDE + kh0 + ch * 8;
                cp_async16(st + r * 80 + ch * 16, pp, valid);
            } else {
                int rl = r - 128;
                cp_async16(st + MATB + rl * 80 + ch * 16,
                           B + (size_t)(bn0 + rl) * BSTRIDE + kh0 + ch * 8, true);
            }
        }
    };

    float acc[MT][4][4];
#pragma unroll
    for (int i = 0; i < MT; i++)
#pragma unroll
        for (int j = 0; j < 4; j++)
#pragma unroll
            for (int k = 0; k < 4; k++) acc[i][j][k] = 0.f;

    issue(0); CP_COMMIT();
    issue(1); CP_COMMIT();

    uint32_t a_row = (uint32_t)(wm * 64 + (lane & 15)) * 80 + (lane >> 4) * 16;
    uint32_t b_row = (uint32_t)(wn * 32 + (lane & 7) + ((lane >> 4) << 3)) * 80 +
                     ((lane >> 3) & 1) * 16;

    for (int c = 0; c < NC; c++) {
        CP_WAIT1();
        __syncthreads();
        uint32_t st = sb + (c & 1) * STAGE;
#pragma unroll
        for (int ks = 0; ks < 2; ks++) {
            uint32_t ko = ks * 32;
            uint32_t Af[MT][4], Bf[2][4];
#pragma unroll
            for (int mt = 0; mt < MT; mt++)
                ldsm4(Af[mt], st + a_row + (uint32_t)mt * (16 * 80) + ko);
#pragma unroll
            for (int nt2 = 0; nt2 < 2; nt2++)
                ldsm4(Bf[nt2], st + MATB + b_row + (uint32_t)nt2 * (16 * 80) + ko);
#pragma unroll
            for (int mt = 0; mt < MT; mt++) {
#pragma unroll
                for (int nt = 0; nt < 4; nt++) {
                    mma16816f16(acc[mt][nt], Af[mt], &Bf[nt >> 1][(nt & 1) * 2]);
                }
            }
        }
        __syncthreads();
        if (c + 2 < NC) issue(c + 2);
        CP_COMMIT();
    }

    int gq = lane >> 2, t4 = lane & 3;
    const float* bias = (MODE == 3) ? W.bias[g] : nullptr;
#pragma unroll
    for (int mt = 0; mt < MT; mt++) {
#pragma unroll
        for (int nt = 0; nt < 4; nt++) {
            int col = wn * 32 + nt * 8 + 2 * t4;
            float b0 = (MODE == 3) ? bias[n0 + col] : 0.f;
            float b1 = (MODE == 3) ? bias[n0 + col + 1] : 0.f;
#pragma unroll
            for (int hrow = 0; hrow < 2; hrow++) {
                int row = m0 + wm * 64 + mt * 16 + gq + hrow * 8;
                if (row < Mlim) {
                    float v0 = acc[mt][nt][2 * hrow + 0];
                    float v1 = acc[mt][nt][2 * hrow + 1];
                    if (MODE == 1) {
                        size_t ob = (size_t)row * 128 + col;
                        __half2 h = __floats2half2_rn(v0, v1);
                        if (y == 0) *(__half2*)(op + ob) = h;
                        else        *(__half2*)(oq + ob) = h;
                    } else if (MODE == 2) {
                        size_t ob = (size_t)row * 256 + n0 + col;
                        *(__half2*)(op + ob) = __floats2half2_rn(v0, v1);
                    } else {
                        size_t ob = (size_t)row * 256 + n0 + col;
                        float2 vv = __half22float2(*(const __half2*)(vin + ob));
                        v0 = fast_tanh(v0 + vv.x + b0);
                        v1 = fast_tanh(v1 + vv.y + b1);
                        *(__half2*)(oh + ob) = __floats2half2_rn(v0, v1);
                    }
                }
            }
        }
    }
}

// ================= host =================
extern "C" void kernel_launch(void* const* d_in, const int* in_sizes, int n_in,
                              void* d_out, int out_size) {
    (void)in_sizes; (void)n_in; (void)out_size;

    const float* x0  = (const float*)d_in[0];
    const float* x1  = (const float*)d_in[1];
    const int*   ei0 = (const int*)d_in[2];
    const int*   ei1 = (const int*)d_in[3];
    const float* W1l_0 = (const float*)d_in[4];
    const float* b1_0  = (const float*)d_in[5];
    const float* W1r_0 = (const float*)d_in[6];
    const float* W2l_0 = (const float*)d_in[7];
    const float* b2_0  = (const float*)d_in[8];
    const float* W2r_0 = (const float*)d_in[9];
    const float* W1l_1 = (const float*)d_in[10];
    const float* b1_1  = (const float*)d_in[11];
    const float* W1r_1 = (const float*)d_in[12];
    const float* W2l_1 = (const float*)d_in[13];
    const float* b2_1  = (const float*)d_in[14];
    const float* W2r_1 = (const float*)d_in[15];
    float* out = (float*)d_out;

    constexpr int SMEM = 2 * 2 * 10240;  // 40960

    int *count, *row_start, *cursor, *srcsort, *btot;
    __half *xh16, *af16, *h16, *v, *p, *q16, *wf16;
    cudaGetSymbolAddress((void**)&count, g_count);
    cudaGetSymbolAddress((void**)&row_start, g_row_start);
    cudaGetSymbolAddress((void**)&cursor, g_cursor);
    cudaGetSymbolAddress((void**)&srcsort, g_srcsort);
    cudaGetSymbolAddress((void**)&btot, g_btot);
    cudaGetSymbolAddress((void**)&xh16, g_xh16);
    cudaGetSymbolAddress((void**)&af16, g_af16);
    cudaGetSymbolAddress((void**)&h16, g_h16);
    cudaGetSymbolAddress((void**)&v, g_v);
    cudaGetSymbolAddress((void**)&p, g_p);
    cudaGetSymbolAddress((void**)&q16, g_q16);
    cudaGetSymbolAddress((void**)&wf16, g_wf16);

    // per-graph split jobs: x_g + W1l_g, W1r_g, W2l_g, W2r_g
    Split5 S[2];
    const float* xs[2] = {x0, x1};
    const float* ws[2][4] = {{W1l_0, W1r_0, W2l_0, W2r_0}, {W1l_1, W1r_1, W2l_1, W2r_1}};
    int cumG[2];
    for (int g = 0; g < 2; g++) {
        int cum = 0;
        S[g].src[0] = xs[g];
        S[g].f16[0] = xh16 + (size_t)g * N_NODES * 128;
        S[g].n4cum[0] = 0;
        cum = N_NODES * 128 / 4;
        for (int j = 0; j < 4; j++) {
            S[g].src[j + 1] = ws[g][j];
            S[g].f16[j + 1] = wf16 + (4 * g + j) * 32768;
            S[g].n4cum[j + 1] = cum;
            cum += 32768 / 4;
        }
        S[g].n4cum[5] = cum;
        cumG[g] = cum;
    }

    GemmW Wv, Wu, W2;
    for (int g = 0; g < 2; g++) {
        for (int y = 0; y < 2; y++) {
            Wv.b0[y][g] = wf16 + (4 * g + 1) * 32768;
            Wv.b1[y][g] = wf16 + (4 * g + 1) * 32768 + 64;
            Wu.b0[y][g] = wf16 + (4 * g + 0) * 32768;
            Wu.b1[y][g] = wf16 + (4 * g + 0) * 32768 + 64;
        }
        W2.b0[0][g] = wf16 + (4 * g + 2) * 32768;
        W2.b1[0][g] = wf16 + (4 * g + 2) * 32768 + 128;
        W2.b0[1][g] = wf16 + (4 * g + 3) * 32768;
        W2.b1[1][g] = wf16 + (4 * g + 3) * 32768 + 128;
    }
    Wu.bias[0] = b1_0; Wu.bias[1] = b1_1;
    Wv.bias[0] = nullptr; Wv.bias[1] = nullptr;
    W2.bias[0] = nullptr; W2.bias[1] = nullptr;

    int* rs0 = row_start;
    int* rs1 = row_start + (N_NODES + 1);
    int* cur0 = cursor;
    int* cur1 = cursor + N_NODES;
    int* cnt0 = count;
    int* cnt1 = count + N_NODES;

    cudaStream_t s2, s3;
    cudaStreamCreateWithFlags(&s2, cudaStreamNonBlocking);
    cudaStreamCreateWithFlags(&s3, cudaStreamNonBlocking);
    cudaEvent_t evFork, evS0, evS1, evV0, evV1, evD1;
    cudaEventCreateWithFlags(&evFork, cudaEventDisableTiming);
    cudaEventCreateWithFlags(&evS0, cudaEventDisableTiming);
    cudaEventCreateWithFlags(&evS1, cudaEventDisableTiming);
    cudaEventCreateWithFlags(&evV0, cudaEventDisableTiming);
    cudaEventCreateWithFlags(&evV1, cudaEventDisableTiming);
    cudaEventCreateWithFlags(&evD1, cudaEventDisableTiming);

    cudaEventRecord(evFork, 0);
    cudaStreamWaitEvent(s2, evFork, 0);
    cudaStreamWaitEvent(s3, evFork, 0);

    // s2: split(g0) -> v(g0) -> split(g1) -> v(g1)
    split5_kernel<<<(cumG[0] + 255) / 256, 256, 0, s2>>>(S[0]);
    cudaEventRecord(evS0, s2);
    {
        dim3 grid(M_TILES, 2, 1);
        sage_mma_kernel<64, 128, 128, 128, 2><<<grid, 256, SMEM, s2>>>(
            xh16, xh16 + 64, Wv, nullptr, v, nullptr, nullptr, 0);
    }
    cudaEventRecord(evV0, s2);
    split5_kernel<<<(cumG[1] + 255) / 256, 256, 0, s2>>>(S[1]);
    cudaEventRecord(evS1, s2);
    {
        dim3 grid(M_TILES, 2, 1);
        sage_mma_kernel<64, 128, 128, 128, 2><<<grid, 256, SMEM, s2>>>(
            xh16, xh16 + 64, Wv, nullptr, v, nullptr, nullptr, 1);
    }
    cudaEventRecord(evV1, s2);

    // ===== graph-0 chain on main =====
    hist_g_kernel<<<(NEDGE / 2 + 255) / 256, 256>>>(ei0, cnt0);
    scan_part_kernel<<<SCAN_BLOCKS_G, 1024>>>(cnt0, rs0, btot);
    scan_add_kernel<<<SCAN_BLOCKS_G, 1024>>>(btot, rs0, cur0, 0);
    scatter_g_kernel<<<(NEDGE / 2 + 255) / 256, 256>>>(ei0, 0, cur0, srcsort);
    cudaStreamWaitEvent(0, evS0, 0);
    aggregate1_kernel<<<N_NODES / 8, 128>>>(xh16, rs0, srcsort, af16, 0);
    cudaStreamWaitEvent(0, evV0, 0);
    {
        dim3 grid(M_TILES, 2, 1);
        sage_mma_kernel<64, 128, 128, 128, 3><<<grid, 256, SMEM>>>(
            af16, af16 + 64, Wu, h16, nullptr, nullptr, v, 0);
        sage_mma_kernel<128, 256, 256, 0, 1><<<grid, 256, SMEM>>>(
            h16, h16 + 128, W2, nullptr, p, q16, nullptr, 0);
    }
    agg_fuse2_kernel<<<N_NODES / 8, 128>>>(p, q16, rs0, srcsort, b2_0, out, 0);

    // ===== graph-1 chain on s3 =====
    hist_g_kernel<<<(NEDGE / 2 + 255) / 256, 256, 0, s3>>>(ei1, cnt1);
    scan_part_kernel<<<SCAN_BLOCKS_G, 1024, 0, s3>>>(cnt1, rs1, btot + SCAN_BLOCKS_G);
    scan_add_kernel<<<SCAN_BLOCKS_G, 1024, 0, s3>>>(btot + SCAN_BLOCKS_G, rs1, cur1, NEDGE);
    scatter_g_kernel<<<(NEDGE / 2 + 255) / 256, 256, 0, s3>>>(ei1, N_NODES, cur1, srcsort);
    cudaStreamWaitEvent(s3, evS1, 0);
    aggregate1_kernel<<<N_NODES / 8, 128, 0, s3>>>(xh16, rs1, srcsort, af16, N_NODES);
    cudaStreamWaitEvent(s3, evV1, 0);
    {
        dim3 grid(M_TILES, 2, 1);
        sage_mma_kernel<64, 128, 128, 128, 3><<<grid, 256, SMEM, s3>>>(
            af16, af16 + 64, Wu, h16, nullptr, nullptr, v, 1);
        sage_mma_kernel<128, 256, 256, 0, 1><<<grid, 256, SMEM, s3>>>(
            h16, h16 + 128, W2, nullptr, p, q16, nullptr, 1);
    }
    agg_fuse2_kernel<<<N_NODES / 8, 128, 0, s3>>>(p, q16, rs1, srcsort, b2_1, out, N_NODES);
    cudaEventRecord(evD1, s3);

    cudaStreamWaitEvent(0, evD1, 0);

    cudaEventDestroy(evFork);
    cudaEventDestroy(evS0);
    cudaEventDestroy(evS1);
    cudaEventDestroy(evV0);
    cudaEventDestroy(evV1);
    cudaEventDestroy(evD1);
    cudaStreamDestroy(s2);
    cudaStreamDestroy(s3);
}

// round 17
// speedup vs baseline: 1.0197x; 1.0122x over previous
#include <cuda_runtime.h>
#include <cuda_fp16.h>
#include <math.h>
#include <stdint.h>

#define N_NODES 50000
#define NTOT    (2 * N_NODES)
#define NEDGE   800000
#define ETOT    (2 * NEDGE)
#define M_TILES ((N_NODES + 127) / 128)   // 391 per graph
#define SCAN_BLOCKS_G ((N_NODES + 1023) / 1024)   // 49 per graph

// ================= device scratch =================
__device__ int   g_count[NTOT];
__device__ int   g_row_start[2 * (N_NODES + 1)];
__device__ int   g_cursor[NTOT];
__device__ int   g_srcsort[ETOT];
__device__ int   g_btot[2 * SCAN_BLOCKS_G];
__device__ __half g_xh16[(size_t)NTOT * 128];
__device__ __half g_af16[(size_t)NTOT * 128];
__device__ __half g_h16[(size_t)NTOT * 256];
__device__ __half g_v[(size_t)NTOT * 256];
__device__ __half g_p[(size_t)NTOT * 128];
__device__ __half g_q16[(size_t)NTOT * 128];
__device__ __half g_wf16[8 * 32768];

// ================= helpers =================
__device__ __forceinline__ uint32_t smem_u32(const void* p) {
    uint32_t a;
    asm("{ .reg .u64 t; cvta.to.shared.u64 t, %1; cvt.u32.u64 %0, t; }" : "=r"(a) : "l"(p));
    return a;
}
__device__ __forceinline__ void cp_async16(uint32_t dst, const void* src, bool valid) {
    if (valid) {
        asm volatile("cp.async.cg.shared.global [%0], [%1], 16;" :: "r"(dst), "l"(src));
    } else {
        asm volatile("cp.async.cg.shared.global [%0], [%1], 16, %2;"
                     :: "r"(dst), "l"(src), "r"(0u));
    }
}
#define CP_COMMIT()  asm volatile("cp.async.commit_group;" ::: "memory")
#define CP_WAIT1()   asm volatile("cp.async.wait_group 1;" ::: "memory")

__device__ __forceinline__ void ldsm4(uint32_t* r, uint32_t addr) {
    asm volatile("ldmatrix.sync.aligned.m8n8.x4.shared.b16 {%0,%1,%2,%3}, [%4];"
                 : "=r"(r[0]), "=r"(r[1]), "=r"(r[2]), "=r"(r[3]) : "r"(addr));
}
__device__ __forceinline__ void mma16816f16(float* d, const uint32_t* a, const uint32_t* b) {
    asm volatile(
        "mma.sync.aligned.m16n8k16.row.col.f32.f16.f16.f32 "
        "{%0,%1,%2,%3}, {%4,%5,%6,%7}, {%8,%9}, {%0,%1,%2,%3};"
        : "+f"(d[0]), "+f"(d[1]), "+f"(d[2]), "+f"(d[3])
        : "r"(a[0]), "r"(a[1]), "r"(a[2]), "r"(a[3]), "r"(b[0]), "r"(b[1]));
}

__device__ __forceinline__ float fast_tanh(float x) {
    float e = __expf(2.0f * x);
    return 1.0f - __fdividef(2.0f, e + 1.0f);
}

// ================= per-graph fp32 -> fp16 conversion (x + 4 weights) =============
struct Split5 {
    const float* src[5];
    __half* f16[5];
    int n4cum[6];
};

__global__ void split5_kernel(Split5 J) {
    int f = blockIdx.x * blockDim.x + threadIdx.x;
    if (f >= J.n4cum[5]) return;
    int j = 0;
#pragma unroll
    for (int t = 0; t < 5; t++)
        if (f >= J.n4cum[t + 1]) j = t + 1;
    int local = f - J.n4cum[j];
    float4 v = *(const float4*)(J.src[j] + 4 * (size_t)local);
    __half2 a = __floats2half2_rn(v.x, v.y);
    __half2 b = __floats2half2_rn(v.z, v.w);
    uint2 pk;
    pk.x = *(uint32_t*)&a;
    pk.y = *(uint32_t*)&b;
    *(uint2*)(J.f16[j] + 4 * (size_t)local) = pk;
}

// ================= per-graph CSR build =================
__global__ void hist_g_kernel(const int* __restrict__ ei, int* __restrict__ count) {
    int t = blockIdx.x * blockDim.x + threadIdx.x;
    int e = t * 2;
    if (e >= NEDGE) return;
    int2 d = *(const int2*)(ei + NEDGE + e);
    atomicAdd(&count[d.x], 1);
    atomicAdd(&count[d.y], 1);
}

// per-block exclusive scan over graph-local counts; zeroes counts; writes block totals
__global__ void scan_part_kernel(int* __restrict__ counts, int* __restrict__ row_start,
                                 int* __restrict__ btot) {
    __shared__ int wsum[32];
    int tid = threadIdx.x, lane = tid & 31, w = tid >> 5;
    int i = blockIdx.x * 1024 + tid;
    int v = 0;
    if (i < N_NODES) { v = counts[i]; counts[i] = 0; }
    int x = v;
#pragma unroll
    for (int off = 1; off < 32; off <<= 1) {
        int t = __shfl_up_sync(0xFFFFFFFFu, x, off);
        if (lane >= off) x += t;
    }
    if (lane == 31) wsum[w] = x;
    __syncthreads();
    if (w == 0) {
        int s = wsum[lane];
#pragma unroll
        for (int off = 1; off < 32; off <<= 1) {
            int t = __shfl_up_sync(0xFFFFFFFFu, s, off);
            if (lane >= off) s += t;
        }
        wsum[lane] = s;
    }
    __syncthreads();
    int excl = x - v + (w ? wsum[w - 1] : 0);
    if (i < N_NODES) row_start[i] = excl;
    if (tid == 0) btot[blockIdx.x] = wsum[31];
}

// each block redundantly scans the 49 block totals (no separate tops kernel),
// adds its offset + edge base; fills row_start[N_NODES] and cursor.
__global__ void scan_add_kernel(const int* __restrict__ btot, int* __restrict__ row_start,
                                int* __restrict__ cursor, int edge_base) {
    __shared__ int sh[64];
    int t = threadIdx.x;
    if (t < 64) sh[t] = (t < SCAN_BLOCKS_G) ? btot[t] : 0;
    __syncthreads();
    for (int off = 1; off < 64; off <<= 1) {
        int v = (t < 64 && t >= off) ? sh[t - off] : 0;
        __syncthreads();
        if (t < 64) sh[t] += v;
        __syncthreads();
    }
    int boff = (blockIdx.x > 0) ? sh[blockIdx.x - 1] : 0;
    int i = blockIdx.x * 1024 + t;
    if (i < N_NODES) {
        int rs = row_start[i] + boff + edge_base;
        row_start[i] = rs;
        cursor[i] = rs;
    }
    if (i == N_NODES - 1) row_start[N_NODES] = edge_base + NEDGE;
}

// 2 edges/thread, vectorized reads
__global__ void scatter_g_kernel(const int* __restrict__ ei, int node_base,
                                 int* __restrict__ cursor, int* __restrict__ srcsort) {
    int t = blockIdx.x * blockDim.x + threadIdx.x;
    int e = t * 2;
    if (e >= NEDGE) return;
    int2 s = *(const int2*)(ei + e);
    int2 d = *(const int2*)(ei + NEDGE + e);
    int p0 = atomicAdd(&cursor[d.x], 1);
    srcsort[p0] = s.x + node_base;
    int p1 = atomicAdd(&cursor[d.y], 1);
    srcsort[p1] = s.y + node_base;
}

// ================= layer-1 mean aggregation (16B loads, 8 nodes/block) ============
__global__ void aggregate1_kernel(const __half* __restrict__ xh,
                                  const int* __restrict__ rs,
                                  const int* __restrict__ srcsort,
                                  __half* __restrict__ oa, int node_base) {
    int local = threadIdx.x >> 4;
    int t8 = (threadIdx.x & 15) * 8;
    int ln = blockIdx.x * 8 + local;
    int node = node_base + ln;
    int s0 = rs[ln];
    int s1 = rs[ln + 1];
    float a[8];
#pragma unroll
    for (int i = 0; i < 8; i++) a[i] = 0.f;
    int e = s0;
    for (; e + 2 <= s1; e += 2) {
        uint4 vA = *(const uint4*)(xh + (size_t)srcsort[e] * 128 + t8);
        uint4 vB = *(const uint4*)(xh + (size_t)srcsort[e + 1] * 128 + t8);
        const uint32_t* wA = &vA.x;
        const uint32_t* wB = &vB.x;
#pragma unroll
        for (int i = 0; i < 4; i++) {
            float2 fA = __half22float2(*(__half2*)&wA[i]);
            float2 fB = __half22float2(*(__half2*)&wB[i]);
            a[2 * i] += fA.x + fB.x;
            a[2 * i + 1] += fA.y + fB.y;
        }
    }
    if (e < s1) {
        uint4 v = *(const uint4*)(xh + (size_t)srcsort[e] * 128 + t8);
        const uint32_t* w = &v.x;
#pragma unroll
        for (int i = 0; i < 4; i++) {
            float2 f = __half22float2(*(__half2*)&w[i]);
            a[2 * i] += f.x;
            a[2 * i + 1] += f.y;
        }
    }
    float inv = 1.0f / (float)max(s1 - s0, 1);
    uint4 pk;
    uint32_t* pw = &pk.x;
#pragma unroll
    for (int i = 0; i < 4; i++) {
        __half2 h = __floats2half2_rn(a[2 * i] * inv, a[2 * i + 1] * inv);
        pw[i] = *(uint32_t*)&h;
    }
    *(uint4*)(oa + (size_t)node * 128 + t8) = pk;
}

// ================= layer-2 fused aggregation + epilogue =================
__global__ void agg_fuse2_kernel(const __half* __restrict__ p,
                                 const __half* __restrict__ q,
                                 const int* __restrict__ rs,
                                 const int* __restrict__ srcsort,
                                 const float* __restrict__ bias,
                                 float* __restrict__ out, int node_base) {
    int local = threadIdx.x >> 4;
    int t8 = (threadIdx.x & 15) * 8;
    int ln = blockIdx.x * 8 + local;
    int node = node_base + ln;
    int s0 = rs[ln];
    int s1 = rs[ln + 1];
    float a[8];
#pragma unroll
    for (int i = 0; i < 8; i++) a[i] = 0.f;
    int e = s0;
    for (; e + 2 <= s1; e += 2) {
        uint4 vA = *(const uint4*)(p + (size_t)srcsort[e] * 128 + t8);
        uint4 vB = *(const uint4*)(p + (size_t)srcsort[e + 1] * 128 + t8);
        const uint32_t* wA = &vA.x;
        const uint32_t* wB = &vB.x;
#pragma unroll
        for (int i = 0; i < 4; i++) {
            float2 fA = __half22float2(*(__half2*)&wA[i]);
            float2 fB = __half22float2(*(__half2*)&wB[i]);
            a[2 * i] += fA.x + fB.x;
            a[2 * i + 1] += fA.y + fB.y;
        }
    }
    if (e < s1) {
        uint4 v = *(const uint4*)(p + (size_t)srcsort[e] * 128 + t8);
        const uint32_t* w = &v.x;
#pragma unroll
        for (int i = 0; i < 4; i++) {
            float2 f = __half22float2(*(__half2*)&w[i]);
            a[2 * i] += f.x;
            a[2 * i + 1] += f.y;
        }
    }
    float inv = 1.0f / (float)max(s1 - s0, 1);
    uint4 qv = *(const uint4*)(q + (size_t)node * 128 + t8);
    const uint32_t* qw = &qv.x;
    float4 b0 = *(const float4*)(bias + t8);
    float4 b1 = *(const float4*)(bias + t8 + 4);
    float qq[8];
#pragma unroll
    for (int i = 0; i < 4; i++) {
        float2 f = __half22float2(*(__half2*)&qw[i]);
        qq[2 * i] = f.x;
        qq[2 * i + 1] = f.y;
    }
    float4 o0, o1;
    o0.x = fast_tanh(a[0] * inv + qq[0] + b0.x);
    o0.y = fast_tanh(a[1] * inv + qq[1] + b0.y);
    o0.z = fast_tanh(a[2] * inv + qq[2] + b0.z);
    o0.w = fast_tanh(a[3] * inv + qq[3] + b0.w);
    o1.x = fast_tanh(a[4] * inv + qq[4] + b1.x);
    o1.y = fast_tanh(a[5] * inv + qq[5] + b1.y);
    o1.z = fast_tanh(a[6] * inv + qq[6] + b1.z);
    o1.w = fast_tanh(a[7] * inv + qq[7] + b1.w);
    *(float4*)(out + (size_t)node * 128 + t8) = o0;
    *(float4*)(out + (size_t)node * 128 + t8 + 4) = o1;
}

// ================= fp16 mma.sync GEMM =================
struct GemmW {
    const __half* b0[2][2];
    const __half* b1[2][2];
    const float* bias[2];
};

// MODE 1: layer2 p/q ; MODE 2: v = x@W1r^T ; MODE 3: h = tanh(acc+v+bias)
template <int KHALF, int ASTRIDE, int BSTRIDE, int BOFF, int MODE>
__global__ void __launch_bounds__(256, 2)
sage_mma_kernel(const __half* __restrict__ a0, const __half* __restrict__ a1,
                GemmW W,
                __half* __restrict__ oh, __half* __restrict__ op,
                __half* __restrict__ oq, const __half* __restrict__ vin, int gbase) {
    constexpr int NC = 2 * KHALF / 32;
    constexpr int MATB = 10240;
    constexpr int STAGE = 2 * MATB;
    constexpr int MT = 4;

    extern __shared__ char smem[];
    uint32_t sb = smem_u32(smem);

    int tid = threadIdx.x;
    int wid = tid >> 5;
    int lane = tid & 31;
    int wm = wid & 1;
    int wn = wid >> 1;
    int y = blockIdx.y;
    int g = gbase + blockIdx.z;
    int m0 = g * N_NODES + blockIdx.x * 128;
    int Mlim = (g + 1) * N_NODES;
    int n0 = y * 128;
    int bn0 = y * BOFF;

    const __half* B0 = W.b0[y][g];
    const __half* B1 = W.b1[y][g];

    auto issue = [&](int c) {
        int half = (c * 32 >= KHALF) ? 1 : 0;
        int kh0 = c * 32 - half * KHALF;
        const __half* A = half ? a1 : a0;
        const __half* B = half ? B1 : B0;
        uint32_t st = sb + (c & 1) * STAGE;
#pragma unroll
        for (int i = 0; i < 4; i++) {
            int idx = i * 256 + tid;
            int r = idx >> 2;
            int ch = idx & 3;
            if (r < 128) {
                int m = m0 + r;
                bool valid = (m < Mlim);
                const __half* pp = A + (size_t)(valid ? m : 0) * ASTRIDE + kh0 + ch * 8;
                cp_async16(st + r * 80 + ch * 16, pp, valid);
            } else {
                int rl = r - 128;
                cp_async16(st + MATB + rl * 80 + ch * 16,
                           B + (size_t)(bn0 + rl) * BSTRIDE + kh0 + ch * 8, true);
            }
        }
    };

    float acc[MT][4][4];
#pragma unroll
    for (int i = 0; i < MT; i++)
#pragma unroll
        for (int j = 0; j < 4; j++)
#pragma unroll
            for (int k = 0; k < 4; k++) acc[i][j][k] = 0.f;

    issue(0); CP_COMMIT();
    issue(1); CP_COMMIT();

    uint32_t a_row = (uint32_t)(wm * 64 + (lane & 15)) * 80 + (lane >> 4) * 16;
    uint32_t b_row = (uint32_t)(wn * 32 + (lane & 7) + ((lane >> 4) << 3)) * 80 +
                     ((lane >> 3) & 1) * 16;

    for (int c = 0; c < NC; c++) {
        CP_WAIT1();
        __syncthreads();
        uint32_t st = sb + (c & 1) * STAGE;
#pragma unroll
        for (int ks = 0; ks < 2; ks++) {
            uint32_t ko = ks * 32;
            uint32_t Af[MT][4], Bf[2][4];
#pragma unroll
            for (int mt = 0; mt < MT; mt++)
                ldsm4(Af[mt], st + a_row + (uint32_t)mt * (16 * 80) + ko);
#pragma unroll
            for (int nt2 = 0; nt2 < 2; nt2++)
                ldsm4(Bf[nt2], st + MATB + b_row + (uint32_t)nt2 * (16 * 80) + ko);
#pragma unroll
            for (int mt = 0; mt < MT; mt++) {
#pragma unroll
                for (int nt = 0; nt < 4; nt++) {
                    mma16816f16(acc[mt][nt], Af[mt], &Bf[nt >> 1][(nt & 1) * 2]);
                }
            }
        }
        __syncthreads();
        if (c + 2 < NC) issue(c + 2);
        CP_COMMIT();
    }

    int gq = lane >> 2, t4 = lane & 3;
    const float* bias = (MODE == 3) ? W.bias[g] : nullptr;
#pragma unroll
    for (int mt = 0; mt < MT; mt++) {
#pragma unroll
        for (int nt = 0; nt < 4; nt++) {
            int col = wn * 32 + nt * 8 + 2 * t4;
            float b0 = (MODE == 3) ? bias[n0 + col] : 0.f;
            float b1 = (MODE == 3) ? bias[n0 + col + 1] : 0.f;
#pragma unroll
            for (int hrow = 0; hrow < 2; hrow++) {
                int row = m0 + wm * 64 + mt * 16 + gq + hrow * 8;
                if (row < Mlim) {
                    float v0 = acc[mt][nt][2 * hrow + 0];
                    float v1 = acc[mt][nt][2 * hrow + 1];
                    if (MODE == 1) {
                        size_t ob = (size_t)row * 128 + col;
                        __half2 h = __floats2half2_rn(v0, v1);
                        if (y == 0) *(__half2*)(op + ob) = h;
                        else        *(__half2*)(oq + ob) = h;
                    } else if (MODE == 2) {
                        size_t ob = (size_t)row * 256 + n0 + col;
                        *(__half2*)(op + ob) = __floats2half2_rn(v0, v1);
                    } else {
                        size_t ob = (size_t)row * 256 + n0 + col;
                        float2 vv = __half22float2(*(const __half2*)(vin + ob));
                        v0 = fast_tanh(v0 + vv.x + b0);
                        v1 = fast_tanh(v1 + vv.y + b1);
                        *(__half2*)(oh + ob) = __floats2half2_rn(v0, v1);
                    }
                }
            }
        }
    }
}

// ================= host =================
extern "C" void kernel_launch(void* const* d_in, const int* in_sizes, int n_in,
                              void* d_out, int out_size) {
    (void)in_sizes; (void)n_in; (void)out_size;

    const float* x0  = (const float*)d_in[0];
    const float* x1  = (const float*)d_in[1];
    const int*   ei0 = (const int*)d_in[2];
    const int*   ei1 = (const int*)d_in[3];
    const float* W1l_0 = (const float*)d_in[4];
    const float* b1_0  = (const float*)d_in[5];
    const float* W1r_0 = (const float*)d_in[6];
    const float* W2l_0 = (const float*)d_in[7];
    const float* b2_0  = (const float*)d_in[8];
    const float* W2r_0 = (const float*)d_in[9];
    const float* W1l_1 = (const float*)d_in[10];
    const float* b1_1  = (const float*)d_in[11];
    const float* W1r_1 = (const float*)d_in[12];
    const float* W2l_1 = (const float*)d_in[13];
    const float* b2_1  = (const float*)d_in[14];
    const float* W2r_1 = (const float*)d_in[15];
    float* out = (float*)d_out;

    constexpr int SMEM = 2 * 2 * 10240;  // 40960

    int *count, *row_start, *cursor, *srcsort, *btot;
    __half *xh16, *af16, *h16, *v, *p, *q16, *wf16;
    cudaGetSymbolAddress((void**)&count, g_count);
    cudaGetSymbolAddress((void**)&row_start, g_row_start);
    cudaGetSymbolAddress((void**)&cursor, g_cursor);
    cudaGetSymbolAddress((void**)&srcsort, g_srcsort);
    cudaGetSymbolAddress((void**)&btot, g_btot);
    cudaGetSymbolAddress((void**)&xh16, g_xh16);
    cudaGetSymbolAddress((void**)&af16, g_af16);
    cudaGetSymbolAddress((void**)&h16, g_h16);
    cudaGetSymbolAddress((void**)&v, g_v);
    cudaGetSymbolAddress((void**)&p, g_p);
    cudaGetSymbolAddress((void**)&q16, g_q16);
    cudaGetSymbolAddress((void**)&wf16, g_wf16);

    // per-graph split jobs: x_g + W1l_g, W1r_g, W2l_g, W2r_g
    Split5 S[2];
    const float* xs[2] = {x0, x1};
    const float* ws[2][4] = {{W1l_0, W1r_0, W2l_0, W2r_0}, {W1l_1, W1r_1, W2l_1, W2r_1}};
    int cumG[2];
    for (int g = 0; g < 2; g++) {
        int cum = 0;
        S[g].src[0] = xs[g];
        S[g].f16[0] = xh16 + (size_t)g * N_NODES * 128;
        S[g].n4cum[0] = 0;
        cum = N_NODES * 128 / 4;
        for (int j = 0; j < 4; j++) {
            S[g].src[j + 1] = ws[g][j];
            S[g].f16[j + 1] = wf16 + (4 * g + j) * 32768;
            S[g].n4cum[j + 1] = cum;
            cum += 32768 / 4;
        }
        S[g].n4cum[5] = cum;
        cumG[g] = cum;
    }

    GemmW Wv, Wu, W2;
    for (int g = 0; g < 2; g++) {
        for (int y = 0; y < 2; y++) {
            Wv.b0[y][g] = wf16 + (4 * g + 1) * 32768;
            Wv.b1[y][g] = wf16 + (4 * g + 1) * 32768 + 64;
            Wu.b0[y][g] = wf16 + (4 * g + 0) * 32768;
            Wu.b1[y][g] = wf16 + (4 * g + 0) * 32768 + 64;
        }
        W2.b0[0][g] = wf16 + (4 * g + 2) * 32768;
        W2.b1[0][g] = wf16 + (4 * g + 2) * 32768 + 128;
        W2.b0[1][g] = wf16 + (4 * g + 3) * 32768;
        W2.b1[1][g] = wf16 + (4 * g + 3) * 32768 + 128;
    }
    Wu.bias[0] = b1_0; Wu.bias[1] = b1_1;
    Wv.bias[0] = nullptr; Wv.bias[1] = nullptr;
    W2.bias[0] = nullptr; W2.bias[1] = nullptr;

    int* rs0 = row_start;
    int* rs1 = row_start + (N_NODES + 1);
    int* cur0 = cursor;
    int* cur1 = cursor + N_NODES;
    int* cnt0 = count;
    int* cnt1 = count + N_NODES;

    cudaStream_t s2, s3;
    cudaStreamCreateWithFlags(&s2, cudaStreamNonBlocking);
    cudaStreamCreateWithFlags(&s3, cudaStreamNonBlocking);
    cudaEvent_t evFork, evS0, evS1, evV0, evV1, evD1;
    cudaEventCreateWithFlags(&evFork, cudaEventDisableTiming);
    cudaEventCreateWithFlags(&evS0, cudaEventDisableTiming);
    cudaEventCreateWithFlags(&evS1, cudaEventDisableTiming);
    cudaEventCreateWithFlags(&evV0, cudaEventDisableTiming);
    cudaEventCreateWithFlags(&evV1, cudaEventDisableTiming);
    cudaEventCreateWithFlags(&evD1, cudaEventDisableTiming);

    cudaEventRecord(evFork, 0);
    cudaStreamWaitEvent(s2, evFork, 0);
    cudaStreamWaitEvent(s3, evFork, 0);

    // s2: split(g0) -> v(g0) -> split(g1) -> v(g1)
    split5_kernel<<<(cumG[0] + 255) / 256, 256, 0, s2>>>(S[0]);
    cudaEventRecord(evS0, s2);
    {
        dim3 grid(M_TILES, 2, 1);
        sage_mma_kernel<64, 128, 128, 128, 2><<<grid, 256, SMEM, s2>>>(
            xh16, xh16 + 64, Wv, nullptr, v, nullptr, nullptr, 0);
    }
    cudaEventRecord(evV0, s2);
    split5_kernel<<<(cumG[1] + 255) / 256, 256, 0, s2>>>(S[1]);
    cudaEventRecord(evS1, s2);
    {
        dim3 grid(M_TILES, 2, 1);
        sage_mma_kernel<64, 128, 128, 128, 2><<<grid, 256, SMEM, s2>>>(
            xh16, xh16 + 64, Wv, nullptr, v, nullptr, nullptr, 1);
    }
    cudaEventRecord(evV1, s2);

    // ===== graph-0 chain on main =====
    hist_g_kernel<<<(NEDGE / 2 + 255) / 256, 256>>>(ei0, cnt0);
    scan_part_kernel<<<SCAN_BLOCKS_G, 1024>>>(cnt0, rs0, btot);
    scan_add_kernel<<<SCAN_BLOCKS_G, 1024>>>(btot, rs0, cur0, 0);
    scatter_g_kernel<<<(NEDGE / 2 + 255) / 256, 256>>>(ei0, 0, cur0, srcsort);
    cudaStreamWaitEvent(0, evS0, 0);
    aggregate1_kernel<<<N_NODES / 8, 128>>>(xh16, rs0, srcsort, af16, 0);
    cudaStreamWaitEvent(0, evV0, 0);
    {
        dim3 grid(M_TILES, 2, 1);
        sage_mma_kernel<64, 128, 128, 128, 3><<<grid, 256, SMEM>>>(
            af16, af16 + 64, Wu, h16, nullptr, nullptr, v, 0);
        sage_mma_kernel<128, 256, 256, 0, 1><<<grid, 256, SMEM>>>(
            h16, h16 + 128, W2, nullptr, p, q16, nullptr, 0);
    }
    agg_fuse2_kernel<<<N_NODES / 8, 128>>>(p, q16, rs0, srcsort, b2_0, out, 0);

    // ===== graph-1 chain on s3 =====
    hist_g_kernel<<<(NEDGE / 2 + 255) / 256, 256, 0, s3>>>(ei1, cnt1);
    scan_part_kernel<<<SCAN_BLOCKS_G, 1024, 0, s3>>>(cnt1, rs1, btot + SCAN_BLOCKS_G);
    scan_add_kernel<<<SCAN_BLOCKS_G, 1024, 0, s3>>>(btot + SCAN_BLOCKS_G, rs1, cur1, NEDGE);
    scatter_g_kernel<<<(NEDGE / 2 + 255) / 256, 256, 0, s3>>>(ei1, N_NODES, cur1, srcsort);
    cudaStreamWaitEvent(s3, evS1, 0);
    aggregate1_kernel<<<N_NODES / 8, 128, 0, s3>>>(xh16, rs1, srcsort, af16, N_NODES);
    cudaStreamWaitEvent(s3, evV1, 0);
    {
        dim3 grid(M_TILES, 2, 1);
        sage_mma_kernel<64, 128, 128, 128, 3><<<grid, 256, SMEM, s3>>>(
            af16, af16 + 64, Wu, h16, nullptr, nullptr, v, 1);
        sage_mma_kernel<128, 256, 256, 0, 1><<<grid, 256, SMEM, s3>>>(
            h16, h16 + 128, W2, nullptr, p, q16, nullptr, 1);
    }
    agg_fuse2_kernel<<<N_NODES / 8, 128, 0, s3>>>(p, q16, rs1, srcsort, b2_1, out, N_NODES);
    cudaEventRecord(evD1, s3);

    cudaStreamWaitEvent(0, evD1, 0);

    cudaEventDestroy(evFork);
    cudaEventDestroy(evS0);
    cudaEventDestroy(evS1);
    cudaEventDestroy(evV0);
    cudaEventDestroy(evV1);
    cudaEventDestroy(evD1);
    cudaStreamDestroy(s2);
    cudaStreamDestroy(s3);
}